// round 11
// baseline (speedup 1.0000x reference)
#include <cuda_runtime.h>
#include <cuda_bf16.h>

#define NN  131072
#define CC  128
#define SS  6
#define BB  6
#define EE  131072
#define ELE 32768
#define GN_EPS 1e-5f

// ---------------- device scratch ----------------
static __device__ float g_bufA[(size_t)NN * CC];
static __device__ float g_bufB[(size_t)NN * CC];
static __device__ float g_temp[(size_t)NN * CC];
// split planes: [N][64] u32 (bf16x2 pairs), hi then lo
static __device__ unsigned g_fhi[(size_t)NN * 64];
static __device__ unsigned g_flo[(size_t)NN * 64];
static __device__ unsigned g_hhi[(size_t)NN * 64];
static __device__ unsigned g_hlo[(size_t)NN * 64];
// split weights: [96][hi 8192 | lo 8192] u32, layout [n=128][kp=64]
static __device__ unsigned g_wsp[(size_t)96 * 16384];

// ---------------- bf16 split helpers ----------------
__device__ __forceinline__ unsigned pack_bf2(__nv_bfloat16 lo16, __nv_bfloat16 hi16) {
    __nv_bfloat162 t(lo16, hi16);
    return *reinterpret_cast<unsigned*>(&t);
}
__device__ __forceinline__ void bsplit(float x, __nv_bfloat16& h, __nv_bfloat16& l) {
    h = __float2bfloat16(x);
    l = __float2bfloat16(x - __bfloat162float(h));
}
__device__ __forceinline__ void split2(float a, float b, unsigned& hi, unsigned& lo) {
    __nv_bfloat16 h0, l0, h1, l1;
    bsplit(a, h0, l0); bsplit(b, h1, l1);
    hi = pack_bf2(h0, h1);
    lo = pack_bf2(l0, l1);
}

__device__ __forceinline__ void mma16816(float acc[4],
                                         unsigned a0, unsigned a1, unsigned a2, unsigned a3,
                                         unsigned b0, unsigned b1) {
    asm volatile(
        "mma.sync.aligned.m16n8k16.row.col.f32.bf16.bf16.f32 "
        "{%0,%1,%2,%3}, {%4,%5,%6,%7}, {%8,%9}, {%0,%1,%2,%3};"
        : "+f"(acc[0]), "+f"(acc[1]), "+f"(acc[2]), "+f"(acc[3])
        : "r"(a0), "r"(a1), "r"(a2), "r"(a3), "r"(b0), "r"(b1));
}
__device__ __forceinline__ void ldsm_x4(unsigned& r0, unsigned& r1, unsigned& r2, unsigned& r3,
                                        unsigned addr) {
    asm volatile("ldmatrix.sync.aligned.m8n8.x4.shared.b16 {%0,%1,%2,%3}, [%4];"
                 : "=r"(r0), "=r"(r1), "=r"(r2), "=r"(r3) : "r"(addr));
}
__device__ __forceinline__ void cp16(unsigned dst_sh, const void* src) {
    asm volatile("cp.async.cg.shared.global [%0], [%1], 16;" :: "r"(dst_sh), "l"(src));
}
__device__ __forceinline__ void mbar_wait(unsigned addr, unsigned parity) {
    asm volatile(
        "{\n\t.reg .pred P1;\n\t"
        "WAIT_LOOP_%=:\n\t"
        "mbarrier.try_wait.parity.acquire.cta.shared::cta.b64 P1, [%0], %1, 0x989680;\n\t"
        "@P1 bra.uni WAIT_DONE_%=;\n\t"
        "bra.uni WAIT_LOOP_%=;\n\t"
        "WAIT_DONE_%=:\n\t}"
        :: "r"(addr), "r"(parity) : "memory");
}

// ---------------- weight pre-split kernel ----------------
__global__ void split_w_kernel(const float* __restrict__ ctr_w, const float* __restrict__ pre_w,
                               const float* __restrict__ suc_w, const float* __restrict__ left_w,
                               const float* __restrict__ right_w, const float* __restrict__ ctr2_w,
                               unsigned* __restrict__ out)
{
    const int m = blockIdx.x;
    const float* W;
    if (m < 6)       W = ctr_w   + (size_t)m        * 16384;
    else if (m < 42) W = pre_w   + (size_t)(m - 6)  * 16384;
    else if (m < 78) W = suc_w   + (size_t)(m - 42) * 16384;
    else if (m < 84) W = left_w  + (size_t)(m - 78) * 16384;
    else if (m < 90) W = right_w + (size_t)(m - 84) * 16384;
    else             W = ctr2_w  + (size_t)(m - 90) * 16384;
    unsigned* hi = out + (size_t)m * 16384;
    unsigned* lo = hi + 8192;
#pragma unroll
    for (int i = 0; i < 32; i++) {
        int p  = threadIdx.x + i * 256;
        int n  = p & 127;
        int kp = p >> 7;
        float w0 = W[(2 * kp) * CC + n];
        float w1 = W[(2 * kp + 1) * CC + n];
        unsigned h, l;
        split2(w0, w1, h, l);
        hi[n * 64 + kp] = h;
        lo[n * 64 + kp] = l;
    }
}

// ---------------- split-half pipelined GEMM machinery ----------------
// CTA = 512 threads = 2 independent halves of 8 warps. Each half: 64-row x 128-col tiles,
// own double-buffered A, own mbarriers, named barrier (1+h). W shared (69.6 KB).
// Row stride 68 u32 (272 B) -> LDSM conflict-free; per-row 256B bulk copies stay linear.
// smem (u32):
//   sW   [0, 17408):      plane*8704 + n*68 + chunk*4
//   sA   [17408, 52224):  half*17408 + slot*8704 + plane*4352 + r*68  (r in [0,64))
//   sIdx [52224, 52736):  half*256 + slot*128 + {u:0-63, v:64-127}
//   mbar [52736, 52744):  4 x u64  (half*2 + slot)
#define SMEM_U32 52744
#define SMEM_BYTES (SMEM_U32 * 4)

template <bool SCATTER>
__device__ __forceinline__ void stage_bulk(unsigned shb, int h, int slot,
                                           const unsigned* __restrict__ Ahi,
                                           const unsigned* __restrict__ Alo,
                                           const int* sV, int row0, int tid_h, unsigned mbar)
{
    if (tid_h == 0)
        asm volatile("mbarrier.arrive.expect_tx.shared.b64 _, [%0], %1;"
                     :: "r"(mbar), "r"(32768u) : "memory");
    if (tid_h < 128) {
        int plane = tid_h >> 6;
        int r = tid_h & 63;
        int src = SCATTER ? sV[r] : (row0 + r);
        const void* srcp = (plane ? Alo : Ahi) + (size_t)src * 64;
        unsigned dst = shb + ((17408u + (unsigned)h * 17408u + (unsigned)slot * 8704u +
                               (unsigned)plane * 4352u + (unsigned)r * 68u) << 2);
        asm volatile(
            "cp.async.bulk.shared::cta.global.mbarrier::complete_tx::bytes [%0], [%1], %2, [%3];"
            :: "r"(dst), "l"(srcp), "r"(256u), "r"(mbar) : "memory");
    }
}

template <bool SCATTER>
__device__ __forceinline__ void gemm_body(unsigned* smem_u, unsigned shb,
                                          const unsigned* __restrict__ Ahi,
                                          const unsigned* __restrict__ Alo,
                                          const unsigned* __restrict__ Wp,
                                          const int* __restrict__ uu,
                                          const int* __restrict__ vv,
                                          float* __restrict__ out,
                                          int n_tiles)
{
    int* sIdx = (int*)(smem_u + 52224);
    const int tid   = threadIdx.x;
    const int lane  = tid & 31;
    const int wid   = tid >> 5;
    const int h     = wid >> 3;         // half id
    const int hw    = wid & 7;          // warp within half
    const int tid_h = tid & 255;
    const int wr    = hw & 1;           // 32-row group within 64-row tile
    const int wc    = hw >> 1;          // 32-col group
    const int tig   = lane & 3;
    const int gid   = lane >> 2;

    const unsigned mbS0 = shb + ((52736u + (unsigned)h * 4u) << 2);
    const unsigned mbS1 = mbS0 + 8u;

    if (tid == 0) {
#pragma unroll
        for (int m = 0; m < 4; m++)
            asm volatile("mbarrier.init.shared.b64 [%0], %1;"
                         :: "r"(shb + ((52736u + (unsigned)m * 2u) << 2)), "r"(1u) : "memory");
    }

    // ---- stage W (shared, padded layout, plain cp.async) ----
    {
        const uint4* wg = (const uint4*)Wp;
#pragma unroll
        for (int j = 0; j < 8; j++) {
            int fi = tid + j * 512;
            int plane = fi >> 11;
            int p = fi & 2047;
            int n = p >> 4;
            int c = p & 15;
            unsigned dst = shb + (((unsigned)plane * 8704u + (unsigned)n * 68u +
                                   (unsigned)c * 4u) << 2);
            cp16(dst, wg + fi);
        }
        asm volatile("cp.async.commit_group;" ::: "memory");
        asm volatile("cp.async.wait_group 0;" ::: "memory");
    }
    __syncthreads();   // W + mbar init visible to all

    int tile = blockIdx.x * 2 + h;
    const int stride = (int)gridDim.x * 2;
    if (tile >= n_tiles) return;

    int* myIdx = sIdx + h * 256;

    // ---- prologue: idx(T0) + stage A(T0) slot 0 ----
    if (SCATTER && tid_h < 128) {
        const int* src = (tid_h < 64) ? uu : vv;
        myIdx[tid_h] = src[(tile << 6) + (tid_h & 63)];
    }
    asm volatile("bar.sync %0, 256;" :: "r"(1 + h) : "memory");
    stage_bulk<SCATTER>(shb, h, 0, Ahi, Alo, myIdx + 64, tile << 6, tid_h, mbS0);

    // ---- fragment address bases ----
    const int hi4A = lane >> 4;
    const int hi4B = (lane & 8) >> 3;
    const bool even = (tig & 1) == 0;
    const int colofs = (tig & 2) ? 4 : 0;
    unsigned baseA[2];
#pragma unroll
    for (int rt = 0; rt < 2; rt++) {
        int rr = wr * 32 + rt * 16 + (lane & 15);   // [0,64)
        baseA[rt] = shb + ((17408u + (unsigned)h * 17408u + (unsigned)rr * 68u) << 2);
    }
    unsigned bBase[2][2];
#pragma unroll
    for (int nt2 = 0; nt2 < 2; nt2++) {
        int nn = wc * 32 + nt2 * 16 + (lane & 7) + ((lane & 16) >> 1);
#pragma unroll
        for (int pl = 0; pl < 2; pl++)
            bBase[nt2][pl] = shb + (((unsigned)pl * 8704u + (unsigned)nn * 68u) << 2);
    }
    const int erow0 = wr * 32 + gid + (even ? 0 : 8);

    int slot = 0;
    unsigned ph0 = 0, ph1 = 0;
#pragma unroll 1
    while (true) {
        const int row0 = tile << 6;
        const int next = tile + stride;
        const bool has_next = (next < n_tiles);

        // early capture of scatter destinations (stable since last named barrier)
        int myU0, myU1;
        if (SCATTER) {
            myU0 = myIdx[slot * 128 + erow0];
            myU1 = myIdx[slot * 128 + erow0 + 16];
        } else {
            myU0 = row0 + erow0;
            myU1 = row0 + erow0 + 16;
        }

        int nreg = 0;
        if (SCATTER && has_next && tid_h < 128) {
            const int* src = (tid_h < 64) ? uu : vv;
            nreg = src[(next << 6) + (tid_h & 63)];
        }

        // wait for A(tile) in current slot
        if (slot == 0) { mbar_wait(mbS0, ph0); ph0 ^= 1; }
        else           { mbar_wait(mbS1, ph1); ph1 ^= 1; }

        if (SCATTER && has_next && tid_h < 128)
            myIdx[(slot ^ 1) * 128 + tid_h] = nreg;
        asm volatile("bar.sync %0, 256;" :: "r"(1 + h) : "memory");

        if (has_next)
            stage_bulk<SCATTER>(shb, h, slot ^ 1, Ahi, Alo, myIdx + (slot ^ 1) * 128 + 64,
                                next << 6, tid_h, slot ? mbS0 : mbS1);

        // ---- compute tile from current slot ----
        const unsigned slotb = (unsigned)slot * 34816u;   // 8704 u32 * 4
        float acc[2][4][4];
#pragma unroll
        for (int rt = 0; rt < 2; rt++)
#pragma unroll
            for (int nt = 0; nt < 4; nt++)
#pragma unroll
                for (int q = 0; q < 4; q++) acc[rt][nt][q] = 0.f;

#pragma unroll
        for (int ks = 0; ks < 8; ks++) {
            unsigned ah[2][4], al[2][4];
#pragma unroll
            for (int rt = 0; rt < 2; rt++) {
                unsigned ch = (unsigned)((2 * ks + hi4A) << 4);
                ldsm_x4(ah[rt][0], ah[rt][1], ah[rt][2], ah[rt][3],
                        baseA[rt] + slotb + ch);
                ldsm_x4(al[rt][0], al[rt][1], al[rt][2], al[rt][3],
                        baseA[rt] + slotb + 17408u + ch);   // lo plane: 4352 u32 * 4
            }
#pragma unroll
            for (int nt2 = 0; nt2 < 2; nt2++) {
                unsigned bh[4], bl[4];
                unsigned ch = (unsigned)((2 * ks + hi4B) << 4);
                ldsm_x4(bh[0], bh[1], bh[2], bh[3], bBase[nt2][0] + ch);
                ldsm_x4(bl[0], bl[1], bl[2], bl[3], bBase[nt2][1] + ch);
#pragma unroll
                for (int half = 0; half < 2; half++) {
                    const int nt = nt2 * 2 + half;
                    unsigned b0h = bh[2 * half], b1h = bh[2 * half + 1];
                    unsigned b0l = bl[2 * half], b1l = bl[2 * half + 1];
#pragma unroll
                    for (int rt = 0; rt < 2; rt++) {
                        mma16816(acc[rt][nt], ah[rt][0], ah[rt][1], ah[rt][2], ah[rt][3], b0h, b1h);
                        mma16816(acc[rt][nt], ah[rt][0], ah[rt][1], ah[rt][2], ah[rt][3], b0l, b1l);
                        mma16816(acc[rt][nt], al[rt][0], al[rt][1], al[rt][2], al[rt][3], b0h, b1h);
                    }
                }
            }
        }

        // ---- epilogue (registers only) ----
#pragma unroll
        for (int rt = 0; rt < 2; rt++) {
            float* base = out + (size_t)(rt ? myU1 : myU0) * CC;
#pragma unroll
            for (int nt = 0; nt < 4; nt++) {
                float c0 = acc[rt][nt][0], c1 = acc[rt][nt][1];
                float c2 = acc[rt][nt][2], c3 = acc[rt][nt][3];
                float e0 = __shfl_xor_sync(0xffffffffu, c0, 1);
                float e1 = __shfl_xor_sync(0xffffffffu, c1, 1);
                float e2 = __shfl_xor_sync(0xffffffffu, c2, 1);
                float e3 = __shfl_xor_sync(0xffffffffu, c3, 1);
                float x0, x1, x2, x3;
                if (even) { x0 = c0; x1 = c1; x2 = e0; x3 = e1; }
                else      { x0 = e2; x1 = e3; x2 = c2; x3 = c3; }
                float* p = base + wc * 32 + nt * 8 + colofs;
                if (SCATTER) {
                    asm volatile("red.global.add.v4.f32 [%0], {%1,%2,%3,%4};"
                                 :: "l"(p), "f"(x0), "f"(x1), "f"(x2), "f"(x3) : "memory");
                } else {
                    float4 v; v.x = x0; v.y = x1; v.z = x2; v.w = x3;
                    *(float4*)p = v;
                }
            }
        }

        if (!has_next) break;
        tile = next;
        slot ^= 1;
    }
}

// ---------------- dense GEMM kernel ----------------
__global__ void __launch_bounds__(512, 1)
msg_dense_kernel(const unsigned* __restrict__ Ahi, const unsigned* __restrict__ Alo,
                 const unsigned* __restrict__ Wp, float* __restrict__ out, int n_rows)
{
    extern __shared__ unsigned smem_u[];
    const unsigned shb = (unsigned)__cvta_generic_to_shared((void*)smem_u);
    gemm_body<false>(smem_u, shb, Ahi, Alo, Wp, nullptr, nullptr, out, n_rows >> 6);
}

// ---------------- scatter GEMM kernel (y-slice picks the edge set) ----------------
__global__ void __launch_bounds__(512, 1)
msg_scatter_kernel(const unsigned* __restrict__ Ahi, const unsigned* __restrict__ Alo,
                   const unsigned* __restrict__ Wbase,  // + blockIdx.y*16384
                   const int* __restrict__ u_idx,       // + blockIdx.y*n_rows
                   const int* __restrict__ v_idx,
                   float* __restrict__ out, int n_rows)
{
    extern __shared__ unsigned smem_u[];
    const unsigned shb = (unsigned)__cvta_generic_to_shared((void*)smem_u);
    const int* uu = u_idx + (size_t)blockIdx.y * n_rows;
    const int* vv = v_idx + (size_t)blockIdx.y * n_rows;
    gemm_body<true>(smem_u, shb, Ahi, Alo, Wbase + (size_t)blockIdx.y * 16384,
                    uu, vv, out, n_rows >> 6);
}

// ---------------- input encoder (+ split write) ----------------
__global__ void encoder_kernel(const float* __restrict__ ctrs, const float* __restrict__ feats,
                               const float* __restrict__ icw0, const float* __restrict__ icb0,
                               const float* __restrict__ icw1, const float* __restrict__ icg,
                               const float* __restrict__ icbt,
                               const float* __restrict__ ifw0, const float* __restrict__ ifb0,
                               const float* __restrict__ ifw1, const float* __restrict__ ifg,
                               const float* __restrict__ ifbt,
                               float* __restrict__ out,
                               unsigned* __restrict__ ohi, unsigned* __restrict__ olo)
{
    const int tid = threadIdx.x;
    const int r = tid >> 7;
    const int c = tid & 127;
    const int row = (blockIdx.x << 1) + r;
    const int warp = (tid >> 5) & 3;
    const int lane = tid & 31;
    __shared__ float sh[2][CC];
    __shared__ float sred[2][2][4];

    float ysum = 0.f;
#pragma unroll
    for (int br = 0; br < 2; br++) {
        const float* x  = br ? feats : ctrs;
        const float* w0 = br ? ifw0 : icw0;
        const float* b0 = br ? ifb0 : icb0;
        const float* w1 = br ? ifw1 : icw1;
        const float* g  = br ? ifg  : icg;
        const float* bt = br ? ifbt : icbt;
        const float x0 = x[row * 2 + 0];
        const float x1 = x[row * 2 + 1];
        float hh = fmaxf(fmaf(x1, w0[CC + c], fmaf(x0, w0[c], b0[c])), 0.f);
        __syncthreads();
        sh[r][c] = hh;
        __syncthreads();
        float z = 0.f;
#pragma unroll 8
        for (int k = 0; k < CC; k++) z = fmaf(sh[r][k], w1[k * CC + c], z);
        float s = z, sq = z * z;
#pragma unroll
        for (int o = 16; o > 0; o >>= 1) {
            s  += __shfl_xor_sync(0xffffffffu, s, o);
            sq += __shfl_xor_sync(0xffffffffu, sq, o);
        }
        if (lane == 0) { sred[r][0][warp] = s; sred[r][1][warp] = sq; }
        __syncthreads();
        float mu  = (sred[r][0][0] + sred[r][0][1] + sred[r][0][2] + sred[r][0][3]) * (1.f / CC);
        float ms  = (sred[r][1][0] + sred[r][1][1] + sred[r][1][2] + sred[r][1][3]) * (1.f / CC);
        float var = ms - mu * mu;
        ysum += (z - mu) * rsqrtf(var + GN_EPS) * g[c] + bt[c];
    }
    float y = fmaxf(ysum, 0.f);
    out[(size_t)row * CC + c] = y;
    float yn = __shfl_down_sync(0xffffffffu, y, 1);
    if ((c & 1) == 0) {
        unsigned hh, ll; split2(y, yn, hh, ll);
        ohi[(size_t)row * 64 + (c >> 1)] = hh;
        olo[(size_t)row * 64 + (c >> 1)] = ll;
    }
}

// ---------------- GN + relu -> split planes only ----------------
__global__ void norm_relu_kernel(const float* __restrict__ in,
                                 const float* __restrict__ g, const float* __restrict__ b,
                                 unsigned* __restrict__ ohi, unsigned* __restrict__ olo)
{
    const int tid = threadIdx.x;
    const int r = tid >> 7, c = tid & 127;
    const size_t row = (size_t)(blockIdx.x << 1) + r;
    const int warp = (tid >> 5) & 3, lane = tid & 31;
    __shared__ float sred[2][2][4];
    float z = in[row * CC + c];
    float s = z, sq = z * z;
#pragma unroll
    for (int o = 16; o > 0; o >>= 1) {
        s  += __shfl_xor_sync(0xffffffffu, s, o);
        sq += __shfl_xor_sync(0xffffffffu, sq, o);
    }
    if (lane == 0) { sred[r][0][warp] = s; sred[r][1][warp] = sq; }
    __syncthreads();
    float mu  = (sred[r][0][0] + sred[r][0][1] + sred[r][0][2] + sred[r][0][3]) * (1.f / CC);
    float ms  = (sred[r][1][0] + sred[r][1][1] + sred[r][1][2] + sred[r][1][3]) * (1.f / CC);
    float var = ms - mu * mu;
    float y = fmaxf((z - mu) * rsqrtf(var + GN_EPS) * g[c] + b[c], 0.f);
    float yn = __shfl_down_sync(0xffffffffu, y, 1);
    if ((c & 1) == 0) {
        unsigned hh, ll; split2(y, yn, hh, ll);
        ohi[row * 64 + (c >> 1)] = hh;
        olo[row * 64 + (c >> 1)] = ll;
    }
}

// ---------------- GN + residual + relu -> f32 + split planes ----------------
__global__ void norm_res_kernel(const float* __restrict__ in,
                                const float* __restrict__ g, const float* __restrict__ b,
                                const float* __restrict__ iden, float* __restrict__ out,
                                unsigned* __restrict__ ohi, unsigned* __restrict__ olo)
{
    const int tid = threadIdx.x;
    const int r = tid >> 7, c = tid & 127;
    const size_t row = (size_t)(blockIdx.x << 1) + r;
    const int warp = (tid >> 5) & 3, lane = tid & 31;
    __shared__ float sred[2][2][4];
    float z = in[row * CC + c];
    float s = z, sq = z * z;
#pragma unroll
    for (int o = 16; o > 0; o >>= 1) {
        s  += __shfl_xor_sync(0xffffffffu, s, o);
        sq += __shfl_xor_sync(0xffffffffu, sq, o);
    }
    if (lane == 0) { sred[r][0][warp] = s; sred[r][1][warp] = sq; }
    __syncthreads();
    float mu  = (sred[r][0][0] + sred[r][0][1] + sred[r][0][2] + sred[r][0][3]) * (1.f / CC);
    float ms  = (sred[r][1][0] + sred[r][1][1] + sred[r][1][2] + sred[r][1][3]) * (1.f / CC);
    float var = ms - mu * mu;
    float y = (z - mu) * rsqrtf(var + GN_EPS) * g[c] + b[c];
    y = fmaxf(y + iden[row * CC + c], 0.f);
    out[row * CC + c] = y;
    float yn = __shfl_down_sync(0xffffffffu, y, 1);
    if ((c & 1) == 0) {
        unsigned hh, ll; split2(y, yn, hh, ll);
        ohi[row * 64 + (c >> 1)] = hh;
        olo[row * 64 + (c >> 1)] = ll;
    }
}

extern "C" void kernel_launch(void* const* d_in, const int* in_sizes, int n_in,
                              void* d_out, int out_size)
{
    const float* ctrs    = (const float*)d_in[0];
    const float* feats   = (const float*)d_in[1];
    const int*   pre_u   = (const int*)d_in[2];
    const int*   pre_v   = (const int*)d_in[3];
    const int*   suc_u   = (const int*)d_in[4];
    const int*   suc_v   = (const int*)d_in[5];
    const int*   left_u  = (const int*)d_in[6];
    const int*   left_v  = (const int*)d_in[7];
    const int*   right_u = (const int*)d_in[8];
    const int*   right_v = (const int*)d_in[9];
    const float* ic_w0   = (const float*)d_in[10];
    const float* ic_b0   = (const float*)d_in[11];
    const float* ic_w1   = (const float*)d_in[12];
    const float* ic_g    = (const float*)d_in[13];
    const float* ic_bt   = (const float*)d_in[14];
    const float* if_w0   = (const float*)d_in[15];
    const float* if_b0   = (const float*)d_in[16];
    const float* if_w1   = (const float*)d_in[17];
    const float* if_g    = (const float*)d_in[18];
    const float* if_bt   = (const float*)d_in[19];
    const float* ctr_w   = (const float*)d_in[20];
    const float* pre_w   = (const float*)d_in[21];
    const float* suc_w   = (const float*)d_in[22];
    const float* left_w  = (const float*)d_in[23];
    const float* right_w = (const float*)d_in[24];
    const float* norm_g  = (const float*)d_in[25];
    const float* norm_b  = (const float*)d_in[26];
    const float* ctr2_w  = (const float*)d_in[27];
    const float* ctr2_g  = (const float*)d_in[28];
    const float* ctr2_b  = (const float*)d_in[29];

    float *bufA, *bufB, *temp;
    unsigned *fhi, *flo, *hhi, *hlo, *wsp;
    cudaGetSymbolAddress((void**)&bufA, g_bufA);
    cudaGetSymbolAddress((void**)&bufB, g_bufB);
    cudaGetSymbolAddress((void**)&temp, g_temp);
    cudaGetSymbolAddress((void**)&fhi, g_fhi);
    cudaGetSymbolAddress((void**)&flo, g_flo);
    cudaGetSymbolAddress((void**)&hhi, g_hhi);
    cudaGetSymbolAddress((void**)&hlo, g_hlo);
    cudaGetSymbolAddress((void**)&wsp, g_wsp);

    cudaFuncSetAttribute(msg_dense_kernel,   cudaFuncAttributeMaxDynamicSharedMemorySize, SMEM_BYTES);
    cudaFuncSetAttribute(msg_scatter_kernel, cudaFuncAttributeMaxDynamicSharedMemorySize, SMEM_BYTES);

    // one-time weight split (96 matrices)
    split_w_kernel<<<96, 256>>>(ctr_w, pre_w, suc_w, left_w, right_w, ctr2_w, wsp);

    // initial feat -> bufA (f32) + split planes
    encoder_kernel<<<NN / 2, 256>>>(ctrs, feats,
                                    ic_w0, ic_b0, ic_w1, ic_g, ic_bt,
                                    if_w0, if_b0, if_w1, if_g, if_bt,
                                    bufA, fhi, flo);

    float* fin = bufA;
    for (int i = 0; i < BB; i++) {
        // temp = feat @ ctr_w[i]
        msg_dense_kernel<<<148, 512, SMEM_BYTES>>>(fhi, flo, wsp + (size_t)i * 16384, temp, NN);
        // scatter-add message passes
        msg_scatter_kernel<<<dim3(74, SS), 512, SMEM_BYTES>>>(
            fhi, flo, wsp + (size_t)(6 + i * 6) * 16384, pre_u, pre_v, temp, EE);
        msg_scatter_kernel<<<dim3(74, SS), 512, SMEM_BYTES>>>(
            fhi, flo, wsp + (size_t)(42 + i * 6) * 16384, suc_u, suc_v, temp, EE);
        msg_scatter_kernel<<<dim3(148, 1), 512, SMEM_BYTES>>>(
            fhi, flo, wsp + (size_t)(78 + i) * 16384, left_u, left_v, temp, ELE);
        msg_scatter_kernel<<<dim3(148, 1), 512, SMEM_BYTES>>>(
            fhi, flo, wsp + (size_t)(84 + i) * 16384, right_u, right_v, temp, ELE);
        // h = relu(GN(temp)) -> split planes
        norm_relu_kernel<<<NN / 2, 256>>>(temp, norm_g + i * CC, norm_b + i * CC, hhi, hlo);
        // temp = h @ ctr2_w[i]
        msg_dense_kernel<<<148, 512, SMEM_BYTES>>>(hhi, hlo, wsp + (size_t)(90 + i) * 16384, temp, NN);
        // feat = relu(GN(temp) + identity)
        float* dst = (i == BB - 1) ? (float*)d_out : ((fin == bufA) ? bufB : bufA);
        norm_res_kernel<<<NN / 2, 256>>>(temp, ctr2_g + i * CC, ctr2_b + i * CC, fin, dst, fhi, flo);
        fin = dst;
    }
}

// round 12
// speedup vs baseline: 1.0738x; 1.0738x over previous
#include <cuda_runtime.h>
#include <cuda_bf16.h>

#define NN  131072
#define CC  128
#define SS  6
#define BB  6
#define EE  131072
#define ELE 32768
#define GN_EPS 1e-5f

// ---------------- device scratch ----------------
static __device__ float g_bufA[(size_t)NN * CC];
static __device__ float g_bufB[(size_t)NN * CC];
static __device__ float g_temp[(size_t)NN * CC];
// split planes: [N][64] u32 (bf16x2 pairs), hi then lo
static __device__ unsigned g_fhi[(size_t)NN * 64];
static __device__ unsigned g_flo[(size_t)NN * 64];
static __device__ unsigned g_hhi[(size_t)NN * 64];
static __device__ unsigned g_hlo[(size_t)NN * 64];
// split weights: [96][hi 8192 | lo 8192] u32, layout [n=128][kp=64]
static __device__ unsigned g_wsp[(size_t)96 * 16384];

// ---------------- bf16 split helpers ----------------
__device__ __forceinline__ unsigned pack_bf2(__nv_bfloat16 lo16, __nv_bfloat16 hi16) {
    __nv_bfloat162 t(lo16, hi16);
    return *reinterpret_cast<unsigned*>(&t);
}
__device__ __forceinline__ void bsplit(float x, __nv_bfloat16& h, __nv_bfloat16& l) {
    h = __float2bfloat16(x);
    l = __float2bfloat16(x - __bfloat162float(h));
}
__device__ __forceinline__ void split2(float a, float b, unsigned& hi, unsigned& lo) {
    __nv_bfloat16 h0, l0, h1, l1;
    bsplit(a, h0, l0); bsplit(b, h1, l1);
    hi = pack_bf2(h0, h1);
    lo = pack_bf2(l0, l1);
}

__device__ __forceinline__ void mma16816(float acc[4],
                                         unsigned a0, unsigned a1, unsigned a2, unsigned a3,
                                         unsigned b0, unsigned b1) {
    asm volatile(
        "mma.sync.aligned.m16n8k16.row.col.f32.bf16.bf16.f32 "
        "{%0,%1,%2,%3}, {%4,%5,%6,%7}, {%8,%9}, {%0,%1,%2,%3};"
        : "+f"(acc[0]), "+f"(acc[1]), "+f"(acc[2]), "+f"(acc[3])
        : "r"(a0), "r"(a1), "r"(a2), "r"(a3), "r"(b0), "r"(b1));
}
__device__ __forceinline__ void ldsm_x4(unsigned& r0, unsigned& r1, unsigned& r2, unsigned& r3,
                                        unsigned addr) {
    asm volatile("ldmatrix.sync.aligned.m8n8.x4.shared.b16 {%0,%1,%2,%3}, [%4];"
                 : "=r"(r0), "=r"(r1), "=r"(r2), "=r"(r3) : "r"(addr));
}
__device__ __forceinline__ void cp16(unsigned dst_sh, const void* src) {
    asm volatile("cp.async.cg.shared.global [%0], [%1], 16;" :: "r"(dst_sh), "l"(src));
}
__device__ __forceinline__ void mbar_wait(unsigned addr, unsigned parity) {
    asm volatile(
        "{\n\t.reg .pred P1;\n\t"
        "WAIT_LOOP_%=:\n\t"
        "mbarrier.try_wait.parity.acquire.cta.shared::cta.b64 P1, [%0], %1, 0x989680;\n\t"
        "@P1 bra.uni WAIT_DONE_%=;\n\t"
        "bra.uni WAIT_LOOP_%=;\n\t"
        "WAIT_DONE_%=:\n\t}"
        :: "r"(addr), "r"(parity) : "memory");
}

// ---------------- weight pre-split kernel ----------------
__global__ void split_w_kernel(const float* __restrict__ ctr_w, const float* __restrict__ pre_w,
                               const float* __restrict__ suc_w, const float* __restrict__ left_w,
                               const float* __restrict__ right_w, const float* __restrict__ ctr2_w,
                               unsigned* __restrict__ out)
{
    const int m = blockIdx.x;
    const float* W;
    if (m < 6)       W = ctr_w   + (size_t)m        * 16384;
    else if (m < 42) W = pre_w   + (size_t)(m - 6)  * 16384;
    else if (m < 78) W = suc_w   + (size_t)(m - 42) * 16384;
    else if (m < 84) W = left_w  + (size_t)(m - 78) * 16384;
    else if (m < 90) W = right_w + (size_t)(m - 84) * 16384;
    else             W = ctr2_w  + (size_t)(m - 90) * 16384;
    unsigned* hi = out + (size_t)m * 16384;
    unsigned* lo = hi + 8192;
#pragma unroll
    for (int i = 0; i < 32; i++) {
        int p  = threadIdx.x + i * 256;
        int n  = p & 127;
        int kp = p >> 7;
        float w0 = W[(2 * kp) * CC + n];
        float w1 = W[(2 * kp + 1) * CC + n];
        unsigned h, l;
        split2(w0, w1, h, l);
        hi[n * 64 + kp] = h;
        lo[n * 64 + kp] = l;
    }
}

// ---------------- bulk-staged GEMM (round-9 proven shape) ----------------
// Tile: 128 rows x 128 cols. 512 threads = 16 warps (4 row-groups x 4 col-groups of 32).
// Row stride 68 u32 (272 B) -> LDSM conflict-free; per-row 256B bulk copies stay linear.
// smem (u32):
//   sW    [0, 17408):      plane*8704 + n*68 + chunk*4
//   sA    [17408, 52224):  slot*17408 + plane*8704 + r*68 + chunk*4
//   sIdx  [52224, 52736):  slot*256 + {u:0-127, v:128-255}
//   mbar  [52736, 52740)
//   GN-S  [52740, 53252)   (fused kernel only: [row][wc] partial sums)
//   GN-Q  [53252, 53764)
//   gamma [53764, 53892)   beta [53892, 54020)
#define SMEM_U32 54020
#define SMEM_BYTES (SMEM_U32 * 4)

template <bool SCATTER>
__device__ __forceinline__ void stage_bulk(unsigned shb, int slot,
                                           const unsigned* __restrict__ Ahi,
                                           const unsigned* __restrict__ Alo,
                                           const int* sV, int row0, int tid, unsigned mbar)
{
    if (tid < 256) {
        int plane = tid >> 7;
        int r = tid & 127;
        int src = SCATTER ? sV[r] : (row0 + r);
        const void* srcp = (plane ? Alo : Ahi) + (size_t)src * 64;
        unsigned dst = shb + ((17408u + (unsigned)slot * 17408u +
                               (unsigned)plane * 8704u + (unsigned)r * 68u) << 2);
        asm volatile("mbarrier.arrive.expect_tx.shared.b64 _, [%0], %1;"
                     :: "r"(mbar), "r"(256u) : "memory");
        asm volatile(
            "cp.async.bulk.shared::cta.global.mbarrier::complete_tx::bytes [%0], [%1], %2, [%3];"
            :: "r"(dst), "l"(srcp), "r"(256u), "r"(mbar) : "memory");
    }
}

// ---------------- round-9 msg_mma_kernel (verbatim behavior) ----------------
template <bool SCATTER>
__global__ void __launch_bounds__(512, 1)
msg_mma_kernel(const unsigned* __restrict__ Ahi,
               const unsigned* __restrict__ Alo,
               const unsigned* __restrict__ Wsp,   // + blockIdx.y*16384
               const int* __restrict__ u_idx,      // + blockIdx.y*n_rows
               const int* __restrict__ v_idx,
               float* __restrict__ out,
               int n_rows)
{
    extern __shared__ unsigned smem_u[];
    int* sIdx = (int*)(smem_u + 52224);

    const int tid  = threadIdx.x;
    const int lane = tid & 31;
    const int wid  = tid >> 5;
    const int wr   = wid & 3;
    const int wc   = wid >> 2;
    const int tig  = lane & 3;
    const int gid  = lane >> 2;

    const int n_tiles = n_rows >> 7;
    int tile = blockIdx.x;
    if (tile >= n_tiles) return;

    const unsigned shb = (unsigned)__cvta_generic_to_shared((void*)smem_u);
    const unsigned mb0 = shb + 52736u * 4u;
    const unsigned mb1 = mb0 + 8u;

    if (tid == 0) {
        asm volatile("mbarrier.init.shared.b64 [%0], %1;" :: "r"(mb0), "r"(256u) : "memory");
        asm volatile("mbarrier.init.shared.b64 [%0], %1;" :: "r"(mb1), "r"(256u) : "memory");
    }
    __syncthreads();

    {
        const uint4* wg = (const uint4*)(Wsp + (size_t)blockIdx.y * 16384);
#pragma unroll
        for (int j = 0; j < 8; j++) {
            int fi = tid + j * 512;
            int plane = fi >> 11;
            int p = fi & 2047;
            int n = p >> 4;
            int c = p & 15;
            unsigned dst = shb + (((unsigned)plane * 8704u + (unsigned)n * 68u +
                                   (unsigned)c * 4u) << 2);
            cp16(dst, wg + fi);
        }
        asm volatile("cp.async.commit_group;" ::: "memory");
    }

    if (SCATTER && tid < 256) {
        const int* src = (tid < 128) ? u_idx : v_idx;
        sIdx[tid] = src[(size_t)blockIdx.y * n_rows + (tile << 7) + (tid & 127)];
    }
    __syncthreads();
    stage_bulk<SCATTER>(shb, 0, Ahi, Alo, sIdx + 128, tile << 7, tid, mb0);

    asm volatile("cp.async.wait_group 0;" ::: "memory");
    __syncthreads();

    const int hi4A = lane >> 4;
    const int hi4B = (lane & 8) >> 3;
    unsigned baseA[2];
#pragma unroll
    for (int rt = 0; rt < 2; rt++) {
        int rr = wr * 32 + rt * 16 + (lane & 15);
        baseA[rt] = shb + ((17408u + (unsigned)rr * 68u) << 2);
    }
    unsigned bBase[2][2];
#pragma unroll
    for (int nt2 = 0; nt2 < 2; nt2++) {
        int nn = wc * 32 + nt2 * 16 + (lane & 7) + ((lane & 16) >> 1);
#pragma unroll
        for (int pl = 0; pl < 2; pl++)
            bBase[nt2][pl] = shb + (((unsigned)pl * 8704u + (unsigned)nn * 68u) << 2);
    }

    int slot = 0;
    unsigned ph0 = 0, ph1 = 0;
#pragma unroll 1
    while (true) {
        const int row0 = tile << 7;
        const int next = tile + gridDim.x;
        const bool has_next = (next < n_tiles);

        int nreg = 0;
        if (SCATTER && has_next && tid < 256) {
            const int* src = (tid < 128) ? u_idx : v_idx;
            nreg = src[(size_t)blockIdx.y * n_rows + (next << 7) + (tid & 127)];
        }

        if (slot == 0) { mbar_wait(mb0, ph0); ph0 ^= 1; }
        else           { mbar_wait(mb1, ph1); ph1 ^= 1; }

        if (SCATTER && has_next && tid < 256)
            sIdx[(slot ^ 1) * 256 + tid] = nreg;
        __syncthreads();

        if (has_next)
            stage_bulk<SCATTER>(shb, slot ^ 1, Ahi, Alo, sIdx + (slot ^ 1) * 256 + 128,
                                next << 7, tid, slot ? mb0 : mb1);

        const unsigned slotb = (unsigned)slot * 69632u;
        float acc[2][4][4];
#pragma unroll
        for (int rt = 0; rt < 2; rt++)
#pragma unroll
            for (int nt = 0; nt < 4; nt++)
#pragma unroll
                for (int q = 0; q < 4; q++) acc[rt][nt][q] = 0.f;

#pragma unroll
        for (int ks = 0; ks < 8; ks++) {
            unsigned ah[2][4], al[2][4];
#pragma unroll
            for (int rt = 0; rt < 2; rt++) {
                unsigned ch = (unsigned)((2 * ks + hi4A) << 4);
                ldsm_x4(ah[rt][0], ah[rt][1], ah[rt][2], ah[rt][3],
                        baseA[rt] + slotb + ch);
                ldsm_x4(al[rt][0], al[rt][1], al[rt][2], al[rt][3],
                        baseA[rt] + slotb + 34816u + ch);
            }
#pragma unroll
            for (int nt2 = 0; nt2 < 2; nt2++) {
                unsigned bh[4], bl[4];
                unsigned ch = (unsigned)((2 * ks + hi4B) << 4);
                ldsm_x4(bh[0], bh[1], bh[2], bh[3], bBase[nt2][0] + ch);
                ldsm_x4(bl[0], bl[1], bl[2], bl[3], bBase[nt2][1] + ch);
#pragma unroll
                for (int half = 0; half < 2; half++) {
                    const int nt = nt2 * 2 + half;
                    unsigned b0h = bh[2 * half], b1h = bh[2 * half + 1];
                    unsigned b0l = bl[2 * half], b1l = bl[2 * half + 1];
#pragma unroll
                    for (int rt = 0; rt < 2; rt++) {
                        mma16816(acc[rt][nt], ah[rt][0], ah[rt][1], ah[rt][2], ah[rt][3], b0h, b1h);
                        mma16816(acc[rt][nt], ah[rt][0], ah[rt][1], ah[rt][2], ah[rt][3], b0l, b1l);
                        mma16816(acc[rt][nt], al[rt][0], al[rt][1], al[rt][2], al[rt][3], b0h, b1h);
                    }
                }
            }
        }

        const bool even = (tig & 1) == 0;
        const int colofs = (tig & 2) ? 4 : 0;
#pragma unroll
        for (int rt = 0; rt < 2; rt++) {
            const int arow = wr * 32 + rt * 16 + gid + (even ? 0 : 8);
            float* base;
            if (SCATTER) base = out + (size_t)sIdx[slot * 256 + arow] * CC;
            else         base = out + (size_t)(row0 + arow) * CC;
#pragma unroll
            for (int nt = 0; nt < 4; nt++) {
                float c0 = acc[rt][nt][0], c1 = acc[rt][nt][1];
                float c2 = acc[rt][nt][2], c3 = acc[rt][nt][3];
                float e0 = __shfl_xor_sync(0xffffffffu, c0, 1);
                float e1 = __shfl_xor_sync(0xffffffffu, c1, 1);
                float e2 = __shfl_xor_sync(0xffffffffu, c2, 1);
                float e3 = __shfl_xor_sync(0xffffffffu, c3, 1);
                float x0, x1, x2, x3;
                if (even) { x0 = c0; x1 = c1; x2 = e0; x3 = e1; }
                else      { x0 = e2; x1 = e3; x2 = c2; x3 = c3; }
                float* p = base + wc * 32 + nt * 8 + colofs;
                if (SCATTER) {
                    asm volatile("red.global.add.v4.f32 [%0], {%1,%2,%3,%4};"
                                 :: "l"(p), "f"(x0), "f"(x1), "f"(x2), "f"(x3) : "memory");
                } else {
                    float4 v; v.x = x0; v.y = x1; v.z = x2; v.w = x3;
                    *(float4*)p = v;
                }
            }
        }

        if (!has_next) break;
        if (SCATTER) __syncthreads();
        tile = next;
        slot ^= 1;
    }
}

// ---------------- fused dense GEMM + GroupNorm + residual + relu + split ----------------
// out_row = relu( GN(h @ W) + iden );  writes f32 out + bf16x2 hi/lo planes. No temp traffic.
__global__ void __launch_bounds__(512, 1)
dense_gn_res_kernel(const unsigned* __restrict__ Ahi,
                    const unsigned* __restrict__ Alo,
                    const unsigned* __restrict__ Wp,
                    const float* __restrict__ gamma, const float* __restrict__ beta,
                    const float* __restrict__ iden,
                    float* __restrict__ outp,
                    unsigned* __restrict__ ohi, unsigned* __restrict__ olo,
                    int n_rows)
{
    extern __shared__ unsigned smem_u[];
    float* sGNS = (float*)(smem_u + 52740);
    float* sGNQ = (float*)(smem_u + 53252);
    float* sGam = (float*)(smem_u + 53764);
    float* sBet = (float*)(smem_u + 53892);

    const int tid  = threadIdx.x;
    const int lane = tid & 31;
    const int wid  = tid >> 5;
    const int wr   = wid & 3;
    const int wc   = wid >> 2;
    const int tig  = lane & 3;
    const int gid  = lane >> 2;

    const int n_tiles = n_rows >> 7;
    int tile = blockIdx.x;
    if (tile >= n_tiles) return;

    const unsigned shb = (unsigned)__cvta_generic_to_shared((void*)smem_u);
    const unsigned mb0 = shb + 52736u * 4u;
    const unsigned mb1 = mb0 + 8u;

    if (tid == 0) {
        asm volatile("mbarrier.init.shared.b64 [%0], %1;" :: "r"(mb0), "r"(256u) : "memory");
        asm volatile("mbarrier.init.shared.b64 [%0], %1;" :: "r"(mb1), "r"(256u) : "memory");
    }
    if (tid < 128)      sGam[tid] = gamma[tid];
    else if (tid < 256) sBet[tid - 128] = beta[tid - 128];
    __syncthreads();

    {
        const uint4* wg = (const uint4*)Wp;
#pragma unroll
        for (int j = 0; j < 8; j++) {
            int fi = tid + j * 512;
            int plane = fi >> 11;
            int p = fi & 2047;
            int n = p >> 4;
            int c = p & 15;
            unsigned dst = shb + (((unsigned)plane * 8704u + (unsigned)n * 68u +
                                   (unsigned)c * 4u) << 2);
            cp16(dst, wg + fi);
        }
        asm volatile("cp.async.commit_group;" ::: "memory");
    }
    stage_bulk<false>(shb, 0, Ahi, Alo, nullptr, tile << 7, tid, mb0);
    asm volatile("cp.async.wait_group 0;" ::: "memory");
    __syncthreads();

    const int hi4A = lane >> 4;
    const int hi4B = (lane & 8) >> 3;
    unsigned baseA[2];
#pragma unroll
    for (int rt = 0; rt < 2; rt++) {
        int rr = wr * 32 + rt * 16 + (lane & 15);
        baseA[rt] = shb + ((17408u + (unsigned)rr * 68u) << 2);
    }
    unsigned bBase[2][2];
#pragma unroll
    for (int nt2 = 0; nt2 < 2; nt2++) {
        int nn = wc * 32 + nt2 * 16 + (lane & 7) + ((lane & 16) >> 1);
#pragma unroll
        for (int pl = 0; pl < 2; pl++)
            bBase[nt2][pl] = shb + (((unsigned)pl * 8704u + (unsigned)nn * 68u) << 2);
    }
    const bool even = (tig & 1) == 0;
    const int colofs = (tig & 2) ? 4 : 0;
    const int erow0 = wr * 32 + gid + (even ? 0 : 8);

    int slot = 0;
    unsigned ph0 = 0, ph1 = 0;
#pragma unroll 1
    while (true) {
        const int row0 = tile << 7;
        const int next = tile + gridDim.x;
        const bool has_next = (next < n_tiles);

        if (slot == 0) { mbar_wait(mb0, ph0); ph0 ^= 1; }
        else           { mbar_wait(mb1, ph1); ph1 ^= 1; }
        __syncthreads();

        if (has_next)
            stage_bulk<false>(shb, slot ^ 1, Ahi, Alo, nullptr, next << 7, tid,
                              slot ? mb0 : mb1);

        const unsigned slotb = (unsigned)slot * 69632u;
        float acc[2][4][4];
#pragma unroll
        for (int rt = 0; rt < 2; rt++)
#pragma unroll
            for (int nt = 0; nt < 4; nt++)
#pragma unroll
                for (int q = 0; q < 4; q++) acc[rt][nt][q] = 0.f;

#pragma unroll
        for (int ks = 0; ks < 8; ks++) {
            unsigned ah[2][4], al[2][4];
#pragma unroll
            for (int rt = 0; rt < 2; rt++) {
                unsigned ch = (unsigned)((2 * ks + hi4A) << 4);
                ldsm_x4(ah[rt][0], ah[rt][1], ah[rt][2], ah[rt][3],
                        baseA[rt] + slotb + ch);
                ldsm_x4(al[rt][0], al[rt][1], al[rt][2], al[rt][3],
                        baseA[rt] + slotb + 34816u + ch);
            }
#pragma unroll
            for (int nt2 = 0; nt2 < 2; nt2++) {
                unsigned bh[4], bl[4];
                unsigned ch = (unsigned)((2 * ks + hi4B) << 4);
                ldsm_x4(bh[0], bh[1], bh[2], bh[3], bBase[nt2][0] + ch);
                ldsm_x4(bl[0], bl[1], bl[2], bl[3], bBase[nt2][1] + ch);
#pragma unroll
                for (int half = 0; half < 2; half++) {
                    const int nt = nt2 * 2 + half;
                    unsigned b0h = bh[2 * half], b1h = bh[2 * half + 1];
                    unsigned b0l = bl[2 * half], b1l = bl[2 * half + 1];
#pragma unroll
                    for (int rt = 0; rt < 2; rt++) {
                        mma16816(acc[rt][nt], ah[rt][0], ah[rt][1], ah[rt][2], ah[rt][3], b0h, b1h);
                        mma16816(acc[rt][nt], ah[rt][0], ah[rt][1], ah[rt][2], ah[rt][3], b0l, b1l);
                        mma16816(acc[rt][nt], al[rt][0], al[rt][1], al[rt][2], al[rt][3], b0h, b1h);
                    }
                }
            }
        }

        // ---- fused epilogue: assemble, row-stats, GN + residual + relu, store ----
        float sP[2] = {0.f, 0.f}, sQ[2] = {0.f, 0.f};
#pragma unroll
        for (int rt = 0; rt < 2; rt++) {
#pragma unroll
            for (int nt = 0; nt < 4; nt++) {
                float c0 = acc[rt][nt][0], c1 = acc[rt][nt][1];
                float c2 = acc[rt][nt][2], c3 = acc[rt][nt][3];
                float e0 = __shfl_xor_sync(0xffffffffu, c0, 1);
                float e1 = __shfl_xor_sync(0xffffffffu, c1, 1);
                float e2 = __shfl_xor_sync(0xffffffffu, c2, 1);
                float e3 = __shfl_xor_sync(0xffffffffu, c3, 1);
                float x0, x1, x2, x3;
                if (even) { x0 = c0; x1 = c1; x2 = e0; x3 = e1; }
                else      { x0 = e2; x1 = e3; x2 = c2; x3 = c3; }
                acc[rt][nt][0] = x0; acc[rt][nt][1] = x1;
                acc[rt][nt][2] = x2; acc[rt][nt][3] = x3;
                sP[rt] += x0 + x1 + x2 + x3;
                sQ[rt] += x0 * x0 + x1 * x1 + x2 * x2 + x3 * x3;
            }
            sP[rt] += __shfl_xor_sync(0xffffffffu, sP[rt], 2);
            sQ[rt] += __shfl_xor_sync(0xffffffffu, sQ[rt], 2);
        }
        if (tig < 2) {
            int rw = wr * 32 + gid + (tig & 1) * 8;     // == erow0 for this lane
#pragma unroll
            for (int rt = 0; rt < 2; rt++) {
                sGNS[(rw + rt * 16) * 4 + wc] = sP[rt];
                sGNQ[(rw + rt * 16) * 4 + wc] = sQ[rt];
            }
        }
        __syncthreads();

#pragma unroll
        for (int rt = 0; rt < 2; rt++) {
            const int row = erow0 + rt * 16;
            float s4 = sGNS[row * 4] + sGNS[row * 4 + 1] + sGNS[row * 4 + 2] + sGNS[row * 4 + 3];
            float q4 = sGNQ[row * 4] + sGNQ[row * 4 + 1] + sGNQ[row * 4 + 2] + sGNQ[row * 4 + 3];
            float mu  = s4 * (1.f / CC);
            float var = q4 * (1.f / CC) - mu * mu;
            float rs  = rsqrtf(var + GN_EPS);
            const size_t grow = (size_t)(row0 + row);
            const float* idrow = iden + grow * CC;
            float* orow = outp + grow * CC;
#pragma unroll
            for (int nt = 0; nt < 4; nt++) {
                const int col0 = wc * 32 + nt * 8 + colofs;
                float4 gg = *(const float4*)(sGam + col0);
                float4 bb = *(const float4*)(sBet + col0);
                float4 id4 = *(const float4*)(idrow + col0);
                float y0 = fmaxf(fmaf((acc[rt][nt][0] - mu) * rs, gg.x, bb.x) + id4.x, 0.f);
                float y1 = fmaxf(fmaf((acc[rt][nt][1] - mu) * rs, gg.y, bb.y) + id4.y, 0.f);
                float y2 = fmaxf(fmaf((acc[rt][nt][2] - mu) * rs, gg.z, bb.z) + id4.z, 0.f);
                float y3 = fmaxf(fmaf((acc[rt][nt][3] - mu) * rs, gg.w, bb.w) + id4.w, 0.f);
                float4 o4; o4.x = y0; o4.y = y1; o4.z = y2; o4.w = y3;
                *(float4*)(orow + col0) = o4;
                unsigned h0, l0, h1, l1;
                split2(y0, y1, h0, l0);
                split2(y2, y3, h1, l1);
                uint2 hv; hv.x = h0; hv.y = h1;
                uint2 lv; lv.x = l0; lv.y = l1;
                *(uint2*)(ohi + grow * 64 + (col0 >> 1)) = hv;
                *(uint2*)(olo + grow * 64 + (col0 >> 1)) = lv;
            }
        }

        if (!has_next) break;
        tile = next;
        slot ^= 1;
    }
}

// ---------------- input encoder (+ split write) ----------------
__global__ void encoder_kernel(const float* __restrict__ ctrs, const float* __restrict__ feats,
                               const float* __restrict__ icw0, const float* __restrict__ icb0,
                               const float* __restrict__ icw1, const float* __restrict__ icg,
                               const float* __restrict__ icbt,
                               const float* __restrict__ ifw0, const float* __restrict__ ifb0,
                               const float* __restrict__ ifw1, const float* __restrict__ ifg,
                               const float* __restrict__ ifbt,
                               float* __restrict__ out,
                               unsigned* __restrict__ ohi, unsigned* __restrict__ olo)
{
    const int tid = threadIdx.x;
    const int r = tid >> 7;
    const int c = tid & 127;
    const int row = (blockIdx.x << 1) + r;
    const int warp = (tid >> 5) & 3;
    const int lane = tid & 31;
    __shared__ float sh[2][CC];
    __shared__ float sred[2][2][4];

    float ysum = 0.f;
#pragma unroll
    for (int br = 0; br < 2; br++) {
        const float* x  = br ? feats : ctrs;
        const float* w0 = br ? ifw0 : icw0;
        const float* b0 = br ? ifb0 : icb0;
        const float* w1 = br ? ifw1 : icw1;
        const float* g  = br ? ifg  : icg;
        const float* bt = br ? ifbt : icbt;
        const float x0 = x[row * 2 + 0];
        const float x1 = x[row * 2 + 1];
        float h = fmaxf(fmaf(x1, w0[CC + c], fmaf(x0, w0[c], b0[c])), 0.f);
        __syncthreads();
        sh[r][c] = h;
        __syncthreads();
        float z = 0.f;
#pragma unroll 8
        for (int k = 0; k < CC; k++) z = fmaf(sh[r][k], w1[k * CC + c], z);
        float s = z, sq = z * z;
#pragma unroll
        for (int o = 16; o > 0; o >>= 1) {
            s  += __shfl_xor_sync(0xffffffffu, s, o);
            sq += __shfl_xor_sync(0xffffffffu, sq, o);
        }
        if (lane == 0) { sred[r][0][warp] = s; sred[r][1][warp] = sq; }
        __syncthreads();
        float mu  = (sred[r][0][0] + sred[r][0][1] + sred[r][0][2] + sred[r][0][3]) * (1.f / CC);
        float ms  = (sred[r][1][0] + sred[r][1][1] + sred[r][1][2] + sred[r][1][3]) * (1.f / CC);
        float var = ms - mu * mu;
        ysum += (z - mu) * rsqrtf(var + GN_EPS) * g[c] + bt[c];
    }
    float y = fmaxf(ysum, 0.f);
    out[(size_t)row * CC + c] = y;
    float yn = __shfl_down_sync(0xffffffffu, y, 1);
    if ((c & 1) == 0) {
        unsigned h, l; split2(y, yn, h, l);
        ohi[(size_t)row * 64 + (c >> 1)] = h;
        olo[(size_t)row * 64 + (c >> 1)] = l;
    }
}

// ---------------- GN + relu -> split planes only ----------------
__global__ void norm_relu_kernel(const float* __restrict__ in,
                                 const float* __restrict__ g, const float* __restrict__ b,
                                 unsigned* __restrict__ ohi, unsigned* __restrict__ olo)
{
    const int tid = threadIdx.x;
    const int r = tid >> 7, c = tid & 127;
    const size_t row = (size_t)(blockIdx.x << 1) + r;
    const int warp = (tid >> 5) & 3, lane = tid & 31;
    __shared__ float sred[2][2][4];
    float z = in[row * CC + c];
    float s = z, sq = z * z;
#pragma unroll
    for (int o = 16; o > 0; o >>= 1) {
        s  += __shfl_xor_sync(0xffffffffu, s, o);
        sq += __shfl_xor_sync(0xffffffffu, sq, o);
    }
    if (lane == 0) { sred[r][0][warp] = s; sred[r][1][warp] = sq; }
    __syncthreads();
    float mu  = (sred[r][0][0] + sred[r][0][1] + sred[r][0][2] + sred[r][0][3]) * (1.f / CC);
    float ms  = (sred[r][1][0] + sred[r][1][1] + sred[r][1][2] + sred[r][1][3]) * (1.f / CC);
    float var = ms - mu * mu;
    float y = fmaxf((z - mu) * rsqrtf(var + GN_EPS) * g[c] + b[c], 0.f);
    float yn = __shfl_down_sync(0xffffffffu, y, 1);
    if ((c & 1) == 0) {
        unsigned h, l; split2(y, yn, h, l);
        ohi[row * 64 + (c >> 1)] = h;
        olo[row * 64 + (c >> 1)] = l;
    }
}

extern "C" void kernel_launch(void* const* d_in, const int* in_sizes, int n_in,
                              void* d_out, int out_size)
{
    const float* ctrs    = (const float*)d_in[0];
    const float* feats   = (const float*)d_in[1];
    const int*   pre_u   = (const int*)d_in[2];
    const int*   pre_v   = (const int*)d_in[3];
    const int*   suc_u   = (const int*)d_in[4];
    const int*   suc_v   = (const int*)d_in[5];
    const int*   left_u  = (const int*)d_in[6];
    const int*   left_v  = (const int*)d_in[7];
    const int*   right_u = (const int*)d_in[8];
    const int*   right_v = (const int*)d_in[9];
    const float* ic_w0   = (const float*)d_in[10];
    const float* ic_b0   = (const float*)d_in[11];
    const float* ic_w1   = (const float*)d_in[12];
    const float* ic_g    = (const float*)d_in[13];
    const float* ic_bt   = (const float*)d_in[14];
    const float* if_w0   = (const float*)d_in[15];
    const float* if_b0   = (const float*)d_in[16];
    const float* if_w1   = (const float*)d_in[17];
    const float* if_g    = (const float*)d_in[18];
    const float* if_bt   = (const float*)d_in[19];
    const float* ctr_w   = (const float*)d_in[20];
    const float* pre_w   = (const float*)d_in[21];
    const float* suc_w   = (const float*)d_in[22];
    const float* left_w  = (const float*)d_in[23];
    const float* right_w = (const float*)d_in[24];
    const float* norm_g  = (const float*)d_in[25];
    const float* norm_b  = (const float*)d_in[26];
    const float* ctr2_w  = (const float*)d_in[27];
    const float* ctr2_g  = (const float*)d_in[28];
    const float* ctr2_b  = (const float*)d_in[29];

    float *bufA, *bufB, *temp;
    unsigned *fhi, *flo, *hhi, *hlo, *wsp;
    cudaGetSymbolAddress((void**)&bufA, g_bufA);
    cudaGetSymbolAddress((void**)&bufB, g_bufB);
    cudaGetSymbolAddress((void**)&temp, g_temp);
    cudaGetSymbolAddress((void**)&fhi, g_fhi);
    cudaGetSymbolAddress((void**)&flo, g_flo);
    cudaGetSymbolAddress((void**)&hhi, g_hhi);
    cudaGetSymbolAddress((void**)&hlo, g_hlo);
    cudaGetSymbolAddress((void**)&wsp, g_wsp);

    cudaFuncSetAttribute(msg_mma_kernel<false>, cudaFuncAttributeMaxDynamicSharedMemorySize, SMEM_BYTES);
    cudaFuncSetAttribute(msg_mma_kernel<true>,  cudaFuncAttributeMaxDynamicSharedMemorySize, SMEM_BYTES);
    cudaFuncSetAttribute(dense_gn_res_kernel,   cudaFuncAttributeMaxDynamicSharedMemorySize, SMEM_BYTES);

    // one-time weight split (96 matrices)
    split_w_kernel<<<96, 256>>>(ctr_w, pre_w, suc_w, left_w, right_w, ctr2_w, wsp);

    // initial feat -> bufA (f32) + split planes
    encoder_kernel<<<NN / 2, 256>>>(ctrs, feats,
                                    ic_w0, ic_b0, ic_w1, ic_g, ic_bt,
                                    if_w0, if_b0, if_w1, if_g, if_bt,
                                    bufA, fhi, flo);

    float* fin = bufA;
    for (int i = 0; i < BB; i++) {
        // temp = feat @ ctr_w[i]
        msg_mma_kernel<false><<<dim3(148, 1), 512, SMEM_BYTES>>>(
            fhi, flo, wsp + (size_t)i * 16384, nullptr, nullptr, temp, NN);
        // scatter-add message passes
        msg_mma_kernel<true><<<dim3(74, SS), 512, SMEM_BYTES>>>(
            fhi, flo, wsp + (size_t)(6 + i * 6) * 16384, pre_u, pre_v, temp, EE);
        msg_mma_kernel<true><<<dim3(74, SS), 512, SMEM_BYTES>>>(
            fhi, flo, wsp + (size_t)(42 + i * 6) * 16384, suc_u, suc_v, temp, EE);
        msg_mma_kernel<true><<<dim3(148, 1), 512, SMEM_BYTES>>>(
            fhi, flo, wsp + (size_t)(78 + i) * 16384, left_u, left_v, temp, ELE);
        msg_mma_kernel<true><<<dim3(148, 1), 512, SMEM_BYTES>>>(
            fhi, flo, wsp + (size_t)(84 + i) * 16384, right_u, right_v, temp, ELE);
        // h = relu(GN(temp)) -> split planes
        norm_relu_kernel<<<NN / 2, 256>>>(temp, norm_g + i * CC, norm_b + i * CC, hhi, hlo);
        // feat = relu(GN(h @ ctr2_w[i]) + identity)  -- fused, no temp round-trip
        float* dst = (i == BB - 1) ? (float*)d_out : ((fin == bufA) ? bufB : bufA);
        dense_gn_res_kernel<<<148, 512, SMEM_BYTES>>>(
            hhi, hlo, wsp + (size_t)(90 + i) * 16384,
            ctr2_g + i * CC, ctr2_b + i * CC, fin, dst, fhi, flo, NN);
        fin = dst;
    }
}

// round 13
// speedup vs baseline: 1.1141x; 1.0376x over previous
#include <cuda_runtime.h>
#include <cuda_bf16.h>

#define NN  131072
#define CC  128
#define SS  6
#define BB  6
#define EE  131072
#define ELE 32768
#define GN_EPS 1e-5f

// ---------------- device scratch ----------------
static __device__ float g_bufA[(size_t)NN * CC];
static __device__ float g_bufB[(size_t)NN * CC];
static __device__ float g_temp[(size_t)NN * CC];
// split planes: [N][64] u32 (bf16x2 pairs), hi then lo
static __device__ unsigned g_fhi[(size_t)NN * 64];
static __device__ unsigned g_flo[(size_t)NN * 64];
// split weights: [96][hi 8192 | lo 8192] u32, layout [n=128][kp=64]
static __device__ unsigned g_wsp[(size_t)96 * 16384];

// ---------------- bf16 split helpers ----------------
__device__ __forceinline__ unsigned pack_bf2(__nv_bfloat16 lo16, __nv_bfloat16 hi16) {
    __nv_bfloat162 t(lo16, hi16);
    return *reinterpret_cast<unsigned*>(&t);
}
__device__ __forceinline__ void bsplit(float x, __nv_bfloat16& h, __nv_bfloat16& l) {
    h = __float2bfloat16(x);
    l = __float2bfloat16(x - __bfloat162float(h));
}
__device__ __forceinline__ void split2(float a, float b, unsigned& hi, unsigned& lo) {
    __nv_bfloat16 h0, l0, h1, l1;
    bsplit(a, h0, l0); bsplit(b, h1, l1);
    hi = pack_bf2(h0, h1);
    lo = pack_bf2(l0, l1);
}

__device__ __forceinline__ void mma16816(float acc[4],
                                         unsigned a0, unsigned a1, unsigned a2, unsigned a3,
                                         unsigned b0, unsigned b1) {
    asm volatile(
        "mma.sync.aligned.m16n8k16.row.col.f32.bf16.bf16.f32 "
        "{%0,%1,%2,%3}, {%4,%5,%6,%7}, {%8,%9}, {%0,%1,%2,%3};"
        : "+f"(acc[0]), "+f"(acc[1]), "+f"(acc[2]), "+f"(acc[3])
        : "r"(a0), "r"(a1), "r"(a2), "r"(a3), "r"(b0), "r"(b1));
}
__device__ __forceinline__ void ldsm_x4(unsigned& r0, unsigned& r1, unsigned& r2, unsigned& r3,
                                        unsigned addr) {
    asm volatile("ldmatrix.sync.aligned.m8n8.x4.shared.b16 {%0,%1,%2,%3}, [%4];"
                 : "=r"(r0), "=r"(r1), "=r"(r2), "=r"(r3) : "r"(addr));
}
__device__ __forceinline__ void cp16(unsigned dst_sh, const void* src) {
    asm volatile("cp.async.cg.shared.global [%0], [%1], 16;" :: "r"(dst_sh), "l"(src));
}
__device__ __forceinline__ void mbar_wait(unsigned addr, unsigned parity) {
    asm volatile(
        "{\n\t.reg .pred P1;\n\t"
        "WAIT_LOOP_%=:\n\t"
        "mbarrier.try_wait.parity.acquire.cta.shared::cta.b64 P1, [%0], %1, 0x989680;\n\t"
        "@P1 bra.uni WAIT_DONE_%=;\n\t"
        "bra.uni WAIT_LOOP_%=;\n\t"
        "WAIT_DONE_%=:\n\t}"
        :: "r"(addr), "r"(parity) : "memory");
}

// ---------------- weight pre-split kernel ----------------
__global__ void split_w_kernel(const float* __restrict__ ctr_w, const float* __restrict__ pre_w,
                               const float* __restrict__ suc_w, const float* __restrict__ left_w,
                               const float* __restrict__ right_w, const float* __restrict__ ctr2_w,
                               unsigned* __restrict__ out)
{
    const int m = blockIdx.x;
    const float* W;
    if (m < 6)       W = ctr_w   + (size_t)m        * 16384;
    else if (m < 42) W = pre_w   + (size_t)(m - 6)  * 16384;
    else if (m < 78) W = suc_w   + (size_t)(m - 42) * 16384;
    else if (m < 84) W = left_w  + (size_t)(m - 78) * 16384;
    else if (m < 90) W = right_w + (size_t)(m - 84) * 16384;
    else             W = ctr2_w  + (size_t)(m - 90) * 16384;
    unsigned* hi = out + (size_t)m * 16384;
    unsigned* lo = hi + 8192;
#pragma unroll
    for (int i = 0; i < 32; i++) {
        int p  = threadIdx.x + i * 256;
        int n  = p & 127;
        int kp = p >> 7;
        float w0 = W[(2 * kp) * CC + n];
        float w1 = W[(2 * kp + 1) * CC + n];
        unsigned h, l;
        split2(w0, w1, h, l);
        hi[n * 64 + kp] = h;
        lo[n * 64 + kp] = l;
    }
}

// ---------------- bulk-staged GEMM (round-9 proven shape) ----------------
// smem (u32):
//   sW    [0, 17408):      plane*8704 + n*68 + chunk*4
//   sA    [17408, 52224):  slot*17408 + plane*8704 + r*68 + chunk*4
//   sIdx  [52224, 52736):  slot*256 + {u:0-127, v:128-255}
//   mbar  [52736, 52740)
#define SMEM_U32 52740
#define SMEM_BYTES (SMEM_U32 * 4)

template <bool SCATTER>
__device__ __forceinline__ void stage_bulk(unsigned shb, int slot,
                                           const unsigned* __restrict__ Ahi,
                                           const unsigned* __restrict__ Alo,
                                           const int* sV, int row0, int tid, unsigned mbar)
{
    if (tid < 256) {
        int plane = tid >> 7;
        int r = tid & 127;
        int src = SCATTER ? sV[r] : (row0 + r);
        const void* srcp = (plane ? Alo : Ahi) + (size_t)src * 64;
        unsigned dst = shb + ((17408u + (unsigned)slot * 17408u +
                               (unsigned)plane * 8704u + (unsigned)r * 68u) << 2);
        asm volatile("mbarrier.arrive.expect_tx.shared.b64 _, [%0], %1;"
                     :: "r"(mbar), "r"(256u) : "memory");
        asm volatile(
            "cp.async.bulk.shared::cta.global.mbarrier::complete_tx::bytes [%0], [%1], %2, [%3];"
            :: "r"(dst), "l"(srcp), "r"(256u), "r"(mbar) : "memory");
    }
}

template <bool SCATTER>
__global__ void __launch_bounds__(512, 1)
msg_mma_kernel(const unsigned* __restrict__ Ahi,
               const unsigned* __restrict__ Alo,
               const unsigned* __restrict__ Wsp,   // + blockIdx.y*16384
               const int* __restrict__ u_idx,      // + blockIdx.y*n_rows
               const int* __restrict__ v_idx,
               float* __restrict__ out,
               int n_rows)
{
    extern __shared__ unsigned smem_u[];
    int* sIdx = (int*)(smem_u + 52224);

    const int tid  = threadIdx.x;
    const int lane = tid & 31;
    const int wid  = tid >> 5;
    const int wr   = wid & 3;
    const int wc   = wid >> 2;
    const int tig  = lane & 3;
    const int gid  = lane >> 2;

    const int n_tiles = n_rows >> 7;
    int tile = blockIdx.x;
    if (tile >= n_tiles) return;

    const unsigned shb = (unsigned)__cvta_generic_to_shared((void*)smem_u);
    const unsigned mb0 = shb + 52736u * 4u;
    const unsigned mb1 = mb0 + 8u;

    if (tid == 0) {
        asm volatile("mbarrier.init.shared.b64 [%0], %1;" :: "r"(mb0), "r"(256u) : "memory");
        asm volatile("mbarrier.init.shared.b64 [%0], %1;" :: "r"(mb1), "r"(256u) : "memory");
    }
    __syncthreads();

    {
        const uint4* wg = (const uint4*)(Wsp + (size_t)blockIdx.y * 16384);
#pragma unroll
        for (int j = 0; j < 8; j++) {
            int fi = tid + j * 512;
            int plane = fi >> 11;
            int p = fi & 2047;
            int n = p >> 4;
            int c = p & 15;
            unsigned dst = shb + (((unsigned)plane * 8704u + (unsigned)n * 68u +
                                   (unsigned)c * 4u) << 2);
            cp16(dst, wg + fi);
        }
        asm volatile("cp.async.commit_group;" ::: "memory");
    }

    if (SCATTER && tid < 256) {
        const int* src = (tid < 128) ? u_idx : v_idx;
        sIdx[tid] = src[(size_t)blockIdx.y * n_rows + (tile << 7) + (tid & 127)];
    }
    __syncthreads();
    stage_bulk<SCATTER>(shb, 0, Ahi, Alo, sIdx + 128, tile << 7, tid, mb0);

    asm volatile("cp.async.wait_group 0;" ::: "memory");
    __syncthreads();

    const int hi4A = lane >> 4;
    const int hi4B = (lane & 8) >> 3;
    unsigned baseA[2];
#pragma unroll
    for (int rt = 0; rt < 2; rt++) {
        int rr = wr * 32 + rt * 16 + (lane & 15);
        baseA[rt] = shb + ((17408u + (unsigned)rr * 68u) << 2);
    }
    unsigned bBase[2][2];
#pragma unroll
    for (int nt2 = 0; nt2 < 2; nt2++) {
        int nn = wc * 32 + nt2 * 16 + (lane & 7) + ((lane & 16) >> 1);
#pragma unroll
        for (int pl = 0; pl < 2; pl++)
            bBase[nt2][pl] = shb + (((unsigned)pl * 8704u + (unsigned)nn * 68u) << 2);
    }

    int slot = 0;
    unsigned ph0 = 0, ph1 = 0;
#pragma unroll 1
    while (true) {
        const int row0 = tile << 7;
        const int next = tile + gridDim.x;
        const bool has_next = (next < n_tiles);

        int nreg = 0;
        if (SCATTER && has_next && tid < 256) {
            const int* src = (tid < 128) ? u_idx : v_idx;
            nreg = src[(size_t)blockIdx.y * n_rows + (next << 7) + (tid & 127)];
        }

        if (slot == 0) { mbar_wait(mb0, ph0); ph0 ^= 1; }
        else           { mbar_wait(mb1, ph1); ph1 ^= 1; }

        if (SCATTER && has_next && tid < 256)
            sIdx[(slot ^ 1) * 256 + tid] = nreg;
        __syncthreads();

        if (has_next)
            stage_bulk<SCATTER>(shb, slot ^ 1, Ahi, Alo, sIdx + (slot ^ 1) * 256 + 128,
                                next << 7, tid, slot ? mb0 : mb1);

        const unsigned slotb = (unsigned)slot * 69632u;
        float acc[2][4][4];
#pragma unroll
        for (int rt = 0; rt < 2; rt++)
#pragma unroll
            for (int nt = 0; nt < 4; nt++)
#pragma unroll
                for (int q = 0; q < 4; q++) acc[rt][nt][q] = 0.f;

#pragma unroll
        for (int ks = 0; ks < 8; ks++) {
            unsigned ah[2][4], al[2][4];
#pragma unroll
            for (int rt = 0; rt < 2; rt++) {
                unsigned ch = (unsigned)((2 * ks + hi4A) << 4);
                ldsm_x4(ah[rt][0], ah[rt][1], ah[rt][2], ah[rt][3],
                        baseA[rt] + slotb + ch);
                ldsm_x4(al[rt][0], al[rt][1], al[rt][2], al[rt][3],
                        baseA[rt] + slotb + 34816u + ch);
            }
#pragma unroll
            for (int nt2 = 0; nt2 < 2; nt2++) {
                unsigned bh[4], bl[4];
                unsigned ch = (unsigned)((2 * ks + hi4B) << 4);
                ldsm_x4(bh[0], bh[1], bh[2], bh[3], bBase[nt2][0] + ch);
                ldsm_x4(bl[0], bl[1], bl[2], bl[3], bBase[nt2][1] + ch);
#pragma unroll
                for (int half = 0; half < 2; half++) {
                    const int nt = nt2 * 2 + half;
                    unsigned b0h = bh[2 * half], b1h = bh[2 * half + 1];
                    unsigned b0l = bl[2 * half], b1l = bl[2 * half + 1];
#pragma unroll
                    for (int rt = 0; rt < 2; rt++) {
                        mma16816(acc[rt][nt], ah[rt][0], ah[rt][1], ah[rt][2], ah[rt][3], b0h, b1h);
                        mma16816(acc[rt][nt], ah[rt][0], ah[rt][1], ah[rt][2], ah[rt][3], b0l, b1l);
                        mma16816(acc[rt][nt], al[rt][0], al[rt][1], al[rt][2], al[rt][3], b0h, b1h);
                    }
                }
            }
        }

        const bool even = (tig & 1) == 0;
        const int colofs = (tig & 2) ? 4 : 0;
#pragma unroll
        for (int rt = 0; rt < 2; rt++) {
            const int arow = wr * 32 + rt * 16 + gid + (even ? 0 : 8);
            float* base;
            if (SCATTER) base = out + (size_t)sIdx[slot * 256 + arow] * CC;
            else         base = out + (size_t)(row0 + arow) * CC;
#pragma unroll
            for (int nt = 0; nt < 4; nt++) {
                float c0 = acc[rt][nt][0], c1 = acc[rt][nt][1];
                float c2 = acc[rt][nt][2], c3 = acc[rt][nt][3];
                float e0 = __shfl_xor_sync(0xffffffffu, c0, 1);
                float e1 = __shfl_xor_sync(0xffffffffu, c1, 1);
                float e2 = __shfl_xor_sync(0xffffffffu, c2, 1);
                float e3 = __shfl_xor_sync(0xffffffffu, c3, 1);
                float x0, x1, x2, x3;
                if (even) { x0 = c0; x1 = c1; x2 = e0; x3 = e1; }
                else      { x0 = e2; x1 = e3; x2 = c2; x3 = c3; }
                float* p = base + wc * 32 + nt * 8 + colofs;
                if (SCATTER) {
                    asm volatile("red.global.add.v4.f32 [%0], {%1,%2,%3,%4};"
                                 :: "l"(p), "f"(x0), "f"(x1), "f"(x2), "f"(x3) : "memory");
                } else {
                    float4 v; v.x = x0; v.y = x1; v.z = x2; v.w = x3;
                    *(float4*)p = v;
                }
            }
        }

        if (!has_next) break;
        if (SCATTER) __syncthreads();
        tile = next;
        slot ^= 1;
    }
}

// ---------------- fully fused: GN1+relu -> GEMM -> GN2 + residual + relu + split ----------------
// y = relu( GN2( relu(GN1(temp)) @ W ) + iden ); writes f32 out + bf16x2 planes.
// smem (u32):
//   sW    [0, 17408)
//   sAf32 [17408, 34304):  r*132 stride, 128 floats/row
//   sAbf  [34304, 51712):  hi 8704 | lo 8704, r*68 stride
//   sGNS  [51712, 52224)   sGNQ [52224, 52736)
//   sG1   [52736, 52864)   sB1 [52864, 52992)  sG2 [52992, 53120)  sB2 [53120, 53248)
//   mbar  [53248, 53250)
#define SMEM2_U32 53252
#define SMEM2_BYTES (SMEM2_U32 * 4)

__global__ void __launch_bounds__(512, 1)
norm_gemm_gn_res_kernel(const float* __restrict__ temp,
                        const unsigned* __restrict__ Wp,
                        const float* __restrict__ g1, const float* __restrict__ b1,
                        const float* __restrict__ g2, const float* __restrict__ b2,
                        const float* __restrict__ iden,
                        float* __restrict__ outp,
                        unsigned* __restrict__ ohi, unsigned* __restrict__ olo,
                        int n_rows)
{
    extern __shared__ unsigned smem_u[];
    float* sGNS = (float*)(smem_u + 51712);
    float* sGNQ = (float*)(smem_u + 52224);
    float* sG1  = (float*)(smem_u + 52736);
    float* sB1  = (float*)(smem_u + 52864);
    float* sG2  = (float*)(smem_u + 52992);
    float* sB2  = (float*)(smem_u + 53120);

    const int tid  = threadIdx.x;
    const int lane = tid & 31;
    const int wid  = tid >> 5;
    const int wr   = wid & 3;
    const int wc   = wid >> 2;
    const int tig  = lane & 3;
    const int gid  = lane >> 2;

    const int n_tiles = n_rows >> 7;
    int tile = blockIdx.x;
    if (tile >= n_tiles) return;

    const unsigned shb = (unsigned)__cvta_generic_to_shared((void*)smem_u);
    const unsigned mb = shb + 53248u * 4u;

    if (tid == 0)
        asm volatile("mbarrier.init.shared.b64 [%0], %1;" :: "r"(mb), "r"(128u) : "memory");
    if (tid < 128)      sG1[tid]       = g1[tid];
    else if (tid < 256) sB1[tid - 128] = b1[tid - 128];
    else if (tid < 384) sG2[tid - 256] = g2[tid - 256];
    else                sB2[tid - 384] = b2[tid - 384];
    __syncthreads();

    // stage W
    {
        const uint4* wg = (const uint4*)Wp;
#pragma unroll
        for (int j = 0; j < 8; j++) {
            int fi = tid + j * 512;
            int plane = fi >> 11;
            int p = fi & 2047;
            int n = p >> 4;
            int c = p & 15;
            unsigned dst = shb + (((unsigned)plane * 8704u + (unsigned)n * 68u +
                                   (unsigned)c * 4u) << 2);
            cp16(dst, wg + fi);
        }
        asm volatile("cp.async.commit_group;" ::: "memory");
    }

    // stage f32 rows of tile 0
    auto stage_f32 = [&](int row0) {
        if (tid < 128) {
            const void* srcp = temp + (size_t)(row0 + tid) * CC;
            unsigned dst = shb + ((17408u + (unsigned)tid * 132u) << 2);
            asm volatile("mbarrier.arrive.expect_tx.shared.b64 _, [%0], %1;"
                         :: "r"(mb), "r"(512u) : "memory");
            asm volatile(
                "cp.async.bulk.shared::cta.global.mbarrier::complete_tx::bytes [%0], [%1], %2, [%3];"
                :: "r"(dst), "l"(srcp), "r"(512u), "r"(mb) : "memory");
        }
    };
    stage_f32(tile << 7);
    asm volatile("cp.async.wait_group 0;" ::: "memory");   // W resident
    __syncthreads();

    // fragment bases: A planes in sAbf
    const int hi4A = lane >> 4;
    const int hi4B = (lane & 8) >> 3;
    unsigned baseA[2];
#pragma unroll
    for (int rt = 0; rt < 2; rt++) {
        int rr = wr * 32 + rt * 16 + (lane & 15);
        baseA[rt] = shb + ((34304u + (unsigned)rr * 68u) << 2);
    }
    unsigned bBase[2][2];
#pragma unroll
    for (int nt2 = 0; nt2 < 2; nt2++) {
        int nn = wc * 32 + nt2 * 16 + (lane & 7) + ((lane & 16) >> 1);
#pragma unroll
        for (int pl = 0; pl < 2; pl++)
            bBase[nt2][pl] = shb + (((unsigned)pl * 8704u + (unsigned)nn * 68u) << 2);
    }
    const bool even = (tig & 1) == 0;
    const int colofs = (tig & 2) ? 4 : 0;
    const int erow0 = wr * 32 + gid + (even ? 0 : 8);

    // convert-role mapping: row = tid>>2, seg = tid&3
    const int cr  = tid >> 2;
    const int cs  = tid & 3;
    float* crow = (float*)(smem_u + 17408) + cr * 132 + cs * 32;
    unsigned* hrow = smem_u + 34304 + cr * 68 + cs * 16;
    unsigned* lrow = hrow + 8704;

    unsigned ph = 0;
#pragma unroll 1
    while (true) {
        const int row0 = tile << 7;
        const int next = tile + gridDim.x;
        const bool has_next = (next < n_tiles);

        mbar_wait(mb, ph); ph ^= 1;

        // ---- GN1 + relu + split -> bf16 planes ----
        {
            float y[32];
#pragma unroll
            for (int j = 0; j < 8; j++) {
                float4 v = *(const float4*)(crow + j * 4);
                y[4 * j] = v.x; y[4 * j + 1] = v.y; y[4 * j + 2] = v.z; y[4 * j + 3] = v.w;
            }
            float s = 0.f, q = 0.f;
#pragma unroll
            for (int j = 0; j < 32; j++) { s += y[j]; q += y[j] * y[j]; }
            s += __shfl_xor_sync(0xffffffffu, s, 1);
            q += __shfl_xor_sync(0xffffffffu, q, 1);
            s += __shfl_xor_sync(0xffffffffu, s, 2);
            q += __shfl_xor_sync(0xffffffffu, q, 2);
            float mu = s * (1.f / CC);
            float var = q * (1.f / CC) - mu * mu;
            float rs = rsqrtf(var + GN_EPS);
            const float* gg = sG1 + cs * 32;
            const float* bb = sB1 + cs * 32;
            unsigned hv[16], lv[16];
#pragma unroll
            for (int j = 0; j < 16; j++) {
                float h0 = fmaxf(fmaf((y[2 * j] - mu) * rs, gg[2 * j], bb[2 * j]), 0.f);
                float h1 = fmaxf(fmaf((y[2 * j + 1] - mu) * rs, gg[2 * j + 1], bb[2 * j + 1]), 0.f);
                split2(h0, h1, hv[j], lv[j]);
            }
#pragma unroll
            for (int j = 0; j < 4; j++) {
                *(uint4*)(hrow + j * 4) = *(uint4*)(hv + j * 4);
                *(uint4*)(lrow + j * 4) = *(uint4*)(lv + j * 4);
            }
        }
        __syncthreads();   // bf16 planes ready; f32 buffer free

        if (has_next) stage_f32(next << 7);

        // ---- MMA ----
        float acc[2][4][4];
#pragma unroll
        for (int rt = 0; rt < 2; rt++)
#pragma unroll
            for (int nt = 0; nt < 4; nt++)
#pragma unroll
                for (int q2 = 0; q2 < 4; q2++) acc[rt][nt][q2] = 0.f;

#pragma unroll
        for (int ks = 0; ks < 8; ks++) {
            unsigned ah[2][4], al[2][4];
#pragma unroll
            for (int rt = 0; rt < 2; rt++) {
                unsigned ch = (unsigned)((2 * ks + hi4A) << 4);
                ldsm_x4(ah[rt][0], ah[rt][1], ah[rt][2], ah[rt][3], baseA[rt] + ch);
                ldsm_x4(al[rt][0], al[rt][1], al[rt][2], al[rt][3], baseA[rt] + 34816u + ch);
            }
#pragma unroll
            for (int nt2 = 0; nt2 < 2; nt2++) {
                unsigned bh[4], bl[4];
                unsigned ch = (unsigned)((2 * ks + hi4B) << 4);
                ldsm_x4(bh[0], bh[1], bh[2], bh[3], bBase[nt2][0] + ch);
                ldsm_x4(bl[0], bl[1], bl[2], bl[3], bBase[nt2][1] + ch);
#pragma unroll
                for (int half = 0; half < 2; half++) {
                    const int nt = nt2 * 2 + half;
                    unsigned b0h = bh[2 * half], b1h = bh[2 * half + 1];
                    unsigned b0l = bl[2 * half], b1l = bl[2 * half + 1];
#pragma unroll
                    for (int rt = 0; rt < 2; rt++) {
                        mma16816(acc[rt][nt], ah[rt][0], ah[rt][1], ah[rt][2], ah[rt][3], b0h, b1h);
                        mma16816(acc[rt][nt], ah[rt][0], ah[rt][1], ah[rt][2], ah[rt][3], b0l, b1l);
                        mma16816(acc[rt][nt], al[rt][0], al[rt][1], al[rt][2], al[rt][3], b0h, b1h);
                    }
                }
            }
        }

        // ---- GN2 + residual + relu epilogue ----
        float sP[2] = {0.f, 0.f}, sQ[2] = {0.f, 0.f};
#pragma unroll
        for (int rt = 0; rt < 2; rt++) {
#pragma unroll
            for (int nt = 0; nt < 4; nt++) {
                float c0 = acc[rt][nt][0], c1 = acc[rt][nt][1];
                float c2 = acc[rt][nt][2], c3 = acc[rt][nt][3];
                float e0 = __shfl_xor_sync(0xffffffffu, c0, 1);
                float e1 = __shfl_xor_sync(0xffffffffu, c1, 1);
                float e2 = __shfl_xor_sync(0xffffffffu, c2, 1);
                float e3 = __shfl_xor_sync(0xffffffffu, c3, 1);
                float x0, x1, x2, x3;
                if (even) { x0 = c0; x1 = c1; x2 = e0; x3 = e1; }
                else      { x0 = e2; x1 = e3; x2 = c2; x3 = c3; }
                acc[rt][nt][0] = x0; acc[rt][nt][1] = x1;
                acc[rt][nt][2] = x2; acc[rt][nt][3] = x3;
                sP[rt] += x0 + x1 + x2 + x3;
                sQ[rt] += x0 * x0 + x1 * x1 + x2 * x2 + x3 * x3;
            }
            sP[rt] += __shfl_xor_sync(0xffffffffu, sP[rt], 2);
            sQ[rt] += __shfl_xor_sync(0xffffffffu, sQ[rt], 2);
        }
        if (tig < 2) {
            int rw = wr * 32 + gid + (tig & 1) * 8;
#pragma unroll
            for (int rt = 0; rt < 2; rt++) {
                sGNS[(rw + rt * 16) * 4 + wc] = sP[rt];
                sGNQ[(rw + rt * 16) * 4 + wc] = sQ[rt];
            }
        }
        __syncthreads();

#pragma unroll
        for (int rt = 0; rt < 2; rt++) {
            const int row = erow0 + rt * 16;
            float s4 = sGNS[row * 4] + sGNS[row * 4 + 1] + sGNS[row * 4 + 2] + sGNS[row * 4 + 3];
            float q4 = sGNQ[row * 4] + sGNQ[row * 4 + 1] + sGNQ[row * 4 + 2] + sGNQ[row * 4 + 3];
            float mu  = s4 * (1.f / CC);
            float var = q4 * (1.f / CC) - mu * mu;
            float rs  = rsqrtf(var + GN_EPS);
            const size_t grow = (size_t)(row0 + row);
            const float* idrow = iden + grow * CC;
            float* orow = outp + grow * CC;
#pragma unroll
            for (int nt = 0; nt < 4; nt++) {
                const int col0 = wc * 32 + nt * 8 + colofs;
                float4 gg = *(const float4*)(sG2 + col0);
                float4 bb = *(const float4*)(sB2 + col0);
                float4 id4 = *(const float4*)(idrow + col0);
                float y0 = fmaxf(fmaf((acc[rt][nt][0] - mu) * rs, gg.x, bb.x) + id4.x, 0.f);
                float y1 = fmaxf(fmaf((acc[rt][nt][1] - mu) * rs, gg.y, bb.y) + id4.y, 0.f);
                float y2 = fmaxf(fmaf((acc[rt][nt][2] - mu) * rs, gg.z, bb.z) + id4.z, 0.f);
                float y3 = fmaxf(fmaf((acc[rt][nt][3] - mu) * rs, gg.w, bb.w) + id4.w, 0.f);
                float4 o4; o4.x = y0; o4.y = y1; o4.z = y2; o4.w = y3;
                *(float4*)(orow + col0) = o4;
                unsigned h0, l0, h1, l1;
                split2(y0, y1, h0, l0);
                split2(y2, y3, h1, l1);
                uint2 hv; hv.x = h0; hv.y = h1;
                uint2 lv; lv.x = l0; lv.y = l1;
                *(uint2*)(ohi + grow * 64 + (col0 >> 1)) = hv;
                *(uint2*)(olo + grow * 64 + (col0 >> 1)) = lv;
            }
        }
        __syncthreads();   // GNS/GNQ + bf16 planes free for next tile

        if (!has_next) break;
        tile = next;
    }
}

// ---------------- input encoder (+ split write) ----------------
__global__ void encoder_kernel(const float* __restrict__ ctrs, const float* __restrict__ feats,
                               const float* __restrict__ icw0, const float* __restrict__ icb0,
                               const float* __restrict__ icw1, const float* __restrict__ icg,
                               const float* __restrict__ icbt,
                               const float* __restrict__ ifw0, const float* __restrict__ ifb0,
                               const float* __restrict__ ifw1, const float* __restrict__ ifg,
                               const float* __restrict__ ifbt,
                               float* __restrict__ out,
                               unsigned* __restrict__ ohi, unsigned* __restrict__ olo)
{
    const int tid = threadIdx.x;
    const int r = tid >> 7;
    const int c = tid & 127;
    const int row = (blockIdx.x << 1) + r;
    const int warp = (tid >> 5) & 3;
    const int lane = tid & 31;
    __shared__ float sh[2][CC];
    __shared__ float sred[2][2][4];

    float ysum = 0.f;
#pragma unroll
    for (int br = 0; br < 2; br++) {
        const float* x  = br ? feats : ctrs;
        const float* w0 = br ? ifw0 : icw0;
        const float* b0 = br ? ifb0 : icb0;
        const float* w1 = br ? ifw1 : icw1;
        const float* g  = br ? ifg  : icg;
        const float* bt = br ? ifbt : icbt;
        const float x0 = x[row * 2 + 0];
        const float x1 = x[row * 2 + 1];
        float h = fmaxf(fmaf(x1, w0[CC + c], fmaf(x0, w0[c], b0[c])), 0.f);
        __syncthreads();
        sh[r][c] = h;
        __syncthreads();
        float z = 0.f;
#pragma unroll 8
        for (int k = 0; k < CC; k++) z = fmaf(sh[r][k], w1[k * CC + c], z);
        float s = z, sq = z * z;
#pragma unroll
        for (int o = 16; o > 0; o >>= 1) {
            s  += __shfl_xor_sync(0xffffffffu, s, o);
            sq += __shfl_xor_sync(0xffffffffu, sq, o);
        }
        if (lane == 0) { sred[r][0][warp] = s; sred[r][1][warp] = sq; }
        __syncthreads();
        float mu  = (sred[r][0][0] + sred[r][0][1] + sred[r][0][2] + sred[r][0][3]) * (1.f / CC);
        float ms  = (sred[r][1][0] + sred[r][1][1] + sred[r][1][2] + sred[r][1][3]) * (1.f / CC);
        float var = ms - mu * mu;
        ysum += (z - mu) * rsqrtf(var + GN_EPS) * g[c] + bt[c];
    }
    float y = fmaxf(ysum, 0.f);
    out[(size_t)row * CC + c] = y;
    float yn = __shfl_down_sync(0xffffffffu, y, 1);
    if ((c & 1) == 0) {
        unsigned h, l; split2(y, yn, h, l);
        ohi[(size_t)row * 64 + (c >> 1)] = h;
        olo[(size_t)row * 64 + (c >> 1)] = l;
    }
}

extern "C" void kernel_launch(void* const* d_in, const int* in_sizes, int n_in,
                              void* d_out, int out_size)
{
    const float* ctrs    = (const float*)d_in[0];
    const float* feats   = (const float*)d_in[1];
    const int*   pre_u   = (const int*)d_in[2];
    const int*   pre_v   = (const int*)d_in[3];
    const int*   suc_u   = (const int*)d_in[4];
    const int*   suc_v   = (const int*)d_in[5];
    const int*   left_u  = (const int*)d_in[6];
    const int*   left_v  = (const int*)d_in[7];
    const int*   right_u = (const int*)d_in[8];
    const int*   right_v = (const int*)d_in[9];
    const float* ic_w0   = (const float*)d_in[10];
    const float* ic_b0   = (const float*)d_in[11];
    const float* ic_w1   = (const float*)d_in[12];
    const float* ic_g    = (const float*)d_in[13];
    const float* ic_bt   = (const float*)d_in[14];
    const float* if_w0   = (const float*)d_in[15];
    const float* if_b0   = (const float*)d_in[16];
    const float* if_w1   = (const float*)d_in[17];
    const float* if_g    = (const float*)d_in[18];
    const float* if_bt   = (const float*)d_in[19];
    const float* ctr_w   = (const float*)d_in[20];
    const float* pre_w   = (const float*)d_in[21];
    const float* suc_w   = (const float*)d_in[22];
    const float* left_w  = (const float*)d_in[23];
    const float* right_w = (const float*)d_in[24];
    const float* norm_g  = (const float*)d_in[25];
    const float* norm_b  = (const float*)d_in[26];
    const float* ctr2_w  = (const float*)d_in[27];
    const float* ctr2_g  = (const float*)d_in[28];
    const float* ctr2_b  = (const float*)d_in[29];

    float *bufA, *bufB, *temp;
    unsigned *fhi, *flo, *wsp;
    cudaGetSymbolAddress((void**)&bufA, g_bufA);
    cudaGetSymbolAddress((void**)&bufB, g_bufB);
    cudaGetSymbolAddress((void**)&temp, g_temp);
    cudaGetSymbolAddress((void**)&fhi, g_fhi);
    cudaGetSymbolAddress((void**)&flo, g_flo);
    cudaGetSymbolAddress((void**)&wsp, g_wsp);

    cudaFuncSetAttribute(msg_mma_kernel<false>, cudaFuncAttributeMaxDynamicSharedMemorySize, SMEM_BYTES);
    cudaFuncSetAttribute(msg_mma_kernel<true>,  cudaFuncAttributeMaxDynamicSharedMemorySize, SMEM_BYTES);
    cudaFuncSetAttribute(norm_gemm_gn_res_kernel, cudaFuncAttributeMaxDynamicSharedMemorySize, SMEM2_BYTES);

    // one-time weight split (96 matrices)
    split_w_kernel<<<96, 256>>>(ctr_w, pre_w, suc_w, left_w, right_w, ctr2_w, wsp);

    // initial feat -> bufA (f32) + split planes
    encoder_kernel<<<NN / 2, 256>>>(ctrs, feats,
                                    ic_w0, ic_b0, ic_w1, ic_g, ic_bt,
                                    if_w0, if_b0, if_w1, if_g, if_bt,
                                    bufA, fhi, flo);

    float* fin = bufA;
    for (int i = 0; i < BB; i++) {
        // temp = feat @ ctr_w[i]
        msg_mma_kernel<false><<<dim3(148, 1), 512, SMEM_BYTES>>>(
            fhi, flo, wsp + (size_t)i * 16384, nullptr, nullptr, temp, NN);
        // scatter-add message passes
        msg_mma_kernel<true><<<dim3(74, SS), 512, SMEM_BYTES>>>(
            fhi, flo, wsp + (size_t)(6 + i * 6) * 16384, pre_u, pre_v, temp, EE);
        msg_mma_kernel<true><<<dim3(74, SS), 512, SMEM_BYTES>>>(
            fhi, flo, wsp + (size_t)(42 + i * 6) * 16384, suc_u, suc_v, temp, EE);
        msg_mma_kernel<true><<<dim3(148, 1), 512, SMEM_BYTES>>>(
            fhi, flo, wsp + (size_t)(78 + i) * 16384, left_u, left_v, temp, ELE);
        msg_mma_kernel<true><<<dim3(148, 1), 512, SMEM_BYTES>>>(
            fhi, flo, wsp + (size_t)(84 + i) * 16384, right_u, right_v, temp, ELE);
        // feat = relu(GN2(relu(GN1(temp)) @ ctr2_w[i]) + identity) -- fully fused
        float* dst = (i == BB - 1) ? (float*)d_out : ((fin == bufA) ? bufB : bufA);
        norm_gemm_gn_res_kernel<<<148, 512, SMEM2_BYTES>>>(
            temp, wsp + (size_t)(90 + i) * 16384,
            norm_g + i * CC, norm_b + i * CC, ctr2_g + i * CC, ctr2_b + i * CC,
            fin, dst, fhi, flo, NN);
        fin = dst;
    }
}